// round 2
// baseline (speedup 1.0000x reference)
#include <cuda_runtime.h>
#include <cstdint>

// Problem constants
#define BATCH   32
#define PLEN    1024
#define DIM     8
#define CS      32          // increments per chunk
#define NC      32          // chunks per batch (CS*NC = 1024 padded increments)
#define SIGLEN  4680        // 8 + 64 + 512 + 4096
#define LVL2_OFF 8
#define LVL3_OFF 72
#define LVL4_OFF 584

// Scratch: ping-pong chunk-signature buffers (device globals — no cudaMalloc allowed)
__device__ float g_buf0[BATCH * NC * SIGLEN];        // ~19.2 MB
__device__ float g_buf1[BATCH * (NC / 2) * SIGLEN];  // ~9.6 MB

// ---------------------------------------------------------------------------
// Kernel 1: per-chunk signature via sequential Horner updates, all in registers.
// Block = (batch, chunk). 512 threads: thread t owns
//   A4[8t .. 8t+7]  (prefix pqr = t), A3[t], A2[t>>3] (= (p,q)), replicated A1[8].
// ---------------------------------------------------------------------------
__global__ __launch_bounds__(512) void sig_chunk_kernel(
    const float* __restrict__ path, float* __restrict__ out)
{
    int bc = blockIdx.x;
    int b  = bc >> 5;       // / NC
    int c  = bc & (NC - 1);

    __shared__ float sx[CS * DIM];   // chunk increments

    int t = threadIdx.x;
    for (int idx = t; idx < CS * DIM; idx += 512) {
        int k   = idx >> 3;
        int dim = idx & 7;
        int i   = c * CS + k;
        float v = 0.0f;
        if (i < PLEN - 1) {
            const float* pp = path + ((size_t)b * PLEN + i) * DIM + dim;
            v = pp[DIM] - pp[0];
        }
        sx[idx] = v;
    }
    __syncthreads();

    int p = t >> 6;
    int q = (t >> 3) & 7;
    int r = t & 7;

    float a4[8] = {0.f,0.f,0.f,0.f,0.f,0.f,0.f,0.f};
    float a1[8] = {0.f,0.f,0.f,0.f,0.f,0.f,0.f,0.f};
    float a3 = 0.f;
    float a2 = 0.f;

    #pragma unroll 4
    for (int k = 0; k < CS; ++k) {
        float x[8];
        #pragma unroll
        for (int s = 0; s < 8; ++s) x[s] = sx[k * 8 + s];

        float xp = x[p], xq = x[q], xr = x[r];
        float a1p = a1[p];

        // Horner factors (use OLD state)
        float t4 = a3 + xr * (a2 * 0.5f + xq * (a1p * (1.0f/6.0f) + xp * (1.0f/24.0f)));
        float t3 = a2 + xq * (a1p * 0.5f + xp * (1.0f/6.0f));

        #pragma unroll
        for (int s = 0; s < 8; ++s) a4[s] = fmaf(x[s], t4, a4[s]);
        a3 = fmaf(xr, t3, a3);
        a2 = fmaf(xq, a1p + xp * 0.5f, a2);
        #pragma unroll
        for (int s = 0; s < 8; ++s) a1[s] += x[s];
    }

    float* base = out + (size_t)bc * SIGLEN;
    if (t < 8)          base[t] = a1[t];
    if ((t & 7) == 0)   base[LVL2_OFF + (t >> 3)] = a2;
    base[LVL3_OFF + t] = a3;
    float4* b4 = reinterpret_cast<float4*>(base + LVL4_OFF);
    b4[2 * t]     = make_float4(a4[0], a4[1], a4[2], a4[3]);
    b4[2 * t + 1] = make_float4(a4[4], a4[5], a4[6], a4[7]);
}

// ---------------------------------------------------------------------------
// Kernel 2: pairwise Chen multiply of full depth-4 signatures.
// C_k = A_k + B_k + sum_{i=1..k-1} A_i (x) B_{k-i}
// FINAL=true writes to d_out in the concatenated-levels layout.
// ---------------------------------------------------------------------------
template <bool FINAL>
__global__ __launch_bounds__(512) void chen_reduce_kernel(
    const float* __restrict__ in, float* __restrict__ out, int cc_in)
{
    int pairs = cc_in >> 1;
    int b = blockIdx.x / pairs;
    int j = blockIdx.x - b * pairs;

    const float* A  = in + (size_t)(b * cc_in + 2 * j) * SIGLEN;
    const float* Bp = A + SIGLEN;

    __shared__ float sB[584];   // B levels 1..3
    __shared__ float sA[72];    // A levels 1..2

    int t = threadIdx.x;
    if (t < 72) sA[t] = A[t];
    for (int i = t; i < 584; i += 512) sB[i] = Bp[i];
    __syncthreads();

    float a1  = sA[t >> 6];
    float a2  = sA[8 + (t >> 3)];
    float a3  = A[LVL3_OFF + t];
    float b3t = sB[LVL3_OFF + t];

    // ---- level 4 (8 elems per thread, float4-vectorized) ----
    const float4* A4 = reinterpret_cast<const float4*>(A  + LVL4_OFF);
    const float4* B4 = reinterpret_cast<const float4*>(Bp + LVL4_OFF);
    int qrs = (t & 63) << 3;
    int rs  = (t & 7) << 3;

    float4 c4out[2];
    #pragma unroll
    for (int h = 0; h < 2; ++h) {
        float4 av = A4[2 * t + h];
        float4 bv = B4[2 * t + h];
        float cv[4];
        const float* af = reinterpret_cast<const float*>(&av);
        const float* bf = reinterpret_cast<const float*>(&bv);
        #pragma unroll
        for (int s4 = 0; s4 < 4; ++s4) {
            int s = h * 4 + s4;
            float cc = af[s4] + bf[s4];
            cc = fmaf(a1, sB[LVL3_OFF + qrs + s], cc);
            cc = fmaf(a2, sB[LVL2_OFF + rs  + s], cc);
            cc = fmaf(a3, sB[s], cc);
            cv[s4] = cc;
        }
        c4out[h] = make_float4(cv[0], cv[1], cv[2], cv[3]);
    }

    // ---- level 3 ----
    float c3 = a3 + b3t + a1 * sB[LVL2_OFF + (t & 63)] + a2 * sB[t & 7];

    if (!FINAL) {
        float* O = out + (size_t)(b * pairs + j) * SIGLEN;
        float4* O4 = reinterpret_cast<float4*>(O + LVL4_OFF);
        O4[2 * t]     = c4out[0];
        O4[2 * t + 1] = c4out[1];
        O[LVL3_OFF + t] = c3;
        if (t < 64) O[LVL2_OFF + t] = sA[8 + t] + sB[8 + t] + sA[t >> 3] * sB[t & 7];
        if (t < 8)  O[t] = sA[t] + sB[t];
    } else {
        // Output layout: [L1 (32*8)] [L2 (32*64)] [L3 (32*512)] [L4 (32*4096)]
        float* o1 = out + (size_t)b * 8;
        float* o2 = out + 256   + (size_t)b * 64;
        float* o3 = out + 2304  + (size_t)b * 512;
        float* o4 = out + 18688 + (size_t)b * 4096;
        float4* O4 = reinterpret_cast<float4*>(o4);
        O4[2 * t]     = c4out[0];
        O4[2 * t + 1] = c4out[1];
        o3[t] = c3;
        if (t < 64) o2[t] = sA[8 + t] + sB[8 + t] + sA[t >> 3] * sB[t & 7];
        if (t < 8)  o1[t] = sA[t] + sB[t];
    }
}

// ---------------------------------------------------------------------------
extern "C" void kernel_launch(void* const* d_in, const int* in_sizes, int n_in,
                              void* d_out, int out_size)
{
    const float* path = (const float*)d_in[0];
    float* out = (float*)d_out;

    float *buf0, *buf1;
    cudaGetSymbolAddress((void**)&buf0, g_buf0);
    cudaGetSymbolAddress((void**)&buf1, g_buf1);

    // 1) per-chunk signatures: 32 batches x 32 chunks
    sig_chunk_kernel<<<BATCH * NC, 512>>>(path, buf0);

    // 2) binary-tree Chen reduction: 32 -> 16 -> 8 -> 4 -> 2 -> 1
    chen_reduce_kernel<false><<<BATCH * 16, 512>>>(buf0, buf1, 32);
    chen_reduce_kernel<false><<<BATCH * 8,  512>>>(buf1, buf0, 16);
    chen_reduce_kernel<false><<<BATCH * 4,  512>>>(buf0, buf1, 8);
    chen_reduce_kernel<false><<<BATCH * 2,  512>>>(buf1, buf0, 4);
    chen_reduce_kernel<true> <<<BATCH,      512>>>(buf0, out, 2);
}

// round 3
// speedup vs baseline: 3.4176x; 3.4176x over previous
#include <cuda_runtime.h>
#include <cstdint>

// Problem constants
#define BATCH   32
#define PLEN    1024
#define DIM     8
#define CS      32          // increments per chunk
#define NC      32          // chunks per batch
#define SIGLEN  4680        // 8 + 64 + 512 + 4096
#define LVL2_OFF 8
#define LVL3_OFF 72
#define LVL4_OFF 584

// Scratch: chunk-signature buffer (device global — no cudaMalloc allowed)
__device__ float g_buf0[BATCH * NC * SIGLEN];   // ~19.2 MB

// ---------------------------------------------------------------------------
// Kernel 1: per-chunk signature via sequential Horner updates.
// Block = (batch, chunk). 512 threads: thread t (= p*64+q*8+r) owns
//   A4[8t..8t+7], A3[t], A2[pq] (threads with r==0 write it), scalar a1p.
// NO dynamic register-array indexing: xp/xq/xr come straight from smem.
// ---------------------------------------------------------------------------
__global__ __launch_bounds__(512) void sig_chunk_kernel(
    const float* __restrict__ path, float* __restrict__ out)
{
    int bc = blockIdx.x;
    int b  = bc >> 5;       // / NC
    int c  = bc & (NC - 1);

    __shared__ float sx[CS * DIM];   // chunk increments, 1 KB

    int t = threadIdx.x;
    {
        // 256 increments * 8 dims / 512 threads -> wait, CS*DIM = 256 floats
        if (t < CS * DIM) {
            int k   = t >> 3;
            int dim = t & 7;
            int i   = c * CS + k;
            float v = 0.0f;
            if (i < PLEN - 1) {
                const float* pp = path + ((size_t)b * PLEN + i) * DIM + dim;
                v = pp[DIM] - pp[0];
            }
            sx[t] = v;
        }
    }
    __syncthreads();

    int p = t >> 6;
    int q = (t >> 3) & 7;
    int r = t & 7;

    float a4[8] = {0.f,0.f,0.f,0.f,0.f,0.f,0.f,0.f};
    float a3 = 0.f;
    float a2 = 0.f;
    float a1p = 0.f;

    #pragma unroll 4
    for (int k = 0; k < CS; ++k) {
        const float4* sx4 = reinterpret_cast<const float4*>(sx + k * 8);
        float4 xlo = sx4[0];
        float4 xhi = sx4[1];
        float xp = sx[k * 8 + p];
        float xq = sx[k * 8 + q];
        float xr = sx[k * 8 + r];

        // Horner factors (use OLD state)
        float t4 = a3 + xr * (a2 * 0.5f + xq * fmaf(xp, (1.0f/24.0f), a1p * (1.0f/6.0f)));
        float t3 = a2 + xq * fmaf(xp, (1.0f/6.0f), a1p * 0.5f);

        a4[0] = fmaf(xlo.x, t4, a4[0]);
        a4[1] = fmaf(xlo.y, t4, a4[1]);
        a4[2] = fmaf(xlo.z, t4, a4[2]);
        a4[3] = fmaf(xlo.w, t4, a4[3]);
        a4[4] = fmaf(xhi.x, t4, a4[4]);
        a4[5] = fmaf(xhi.y, t4, a4[5]);
        a4[6] = fmaf(xhi.z, t4, a4[6]);
        a4[7] = fmaf(xhi.w, t4, a4[7]);
        a3 = fmaf(xr, t3, a3);
        a2 = fmaf(xq, fmaf(xp, 0.5f, a1p), a2);
        a1p += xp;
    }

    float* base = out + (size_t)bc * SIGLEN;
    if (t < 8) {
        // chunk level-1 = telescoping sum of increments = path[end]-path[start]
        int istart = c * CS;
        int iend   = min(istart + CS, PLEN - 1);
        const float* pb = path + (size_t)b * PLEN * DIM;
        base[t] = pb[(size_t)iend * DIM + t] - pb[(size_t)istart * DIM + t];
    }
    if (r == 0) base[LVL2_OFF + (t >> 3)] = a2;
    base[LVL3_OFF + t] = a3;
    float4* b4 = reinterpret_cast<float4*>(base + LVL4_OFF);
    b4[2 * t]     = make_float4(a4[0], a4[1], a4[2], a4[3]);
    b4[2 * t + 1] = make_float4(a4[4], a4[5], a4[6], a4[7]);
}

// ---------------------------------------------------------------------------
// Kernel 2: per-batch SEQUENTIAL Chen reduction of NC chunk signatures.
// One block per batch, 512 threads. State: L4 slice (8 regs) + L3 (1 reg)
// per thread; L1/L2 in shared. Next chunk's signature prefetched into
// registers to hide L2 latency. Writes final concatenated output.
//   C = A (x) B:  C4 = A4+B4 + A1(x)B3 + A2(x)B2 + A3(x)B1
//                 C3 = A3+B3 + A1(x)B2 + A2(x)B1
//                 C2 = A2+B2 + A1(x)B1
//                 C1 = A1+B1
// ---------------------------------------------------------------------------
__global__ __launch_bounds__(512) void chen_seq_kernel(
    const float* __restrict__ in, float* __restrict__ out)
{
    int b = blockIdx.x;
    int t = threadIdx.x;
    int p = t >> 6;
    int qr = t & 63;
    int r = t & 7;

    __shared__ float cL1[8];
    __shared__ float cL2[64];
    __shared__ float sB[584];     // B levels 1..3 of current multiplicand

    const float* S = in + (size_t)b * NC * SIGLEN;

    // ---- init state from chunk 0 ----
    float c4[8];
    {
        const float4* A4 = reinterpret_cast<const float4*>(S + LVL4_OFF);
        float4 lo = A4[2 * t], hi = A4[2 * t + 1];
        c4[0]=lo.x; c4[1]=lo.y; c4[2]=lo.z; c4[3]=lo.w;
        c4[4]=hi.x; c4[5]=hi.y; c4[6]=hi.z; c4[7]=hi.w;
    }
    float c3 = S[LVL3_OFF + t];
    if (t < 8)  cL1[t] = S[t];
    if (t < 64) cL2[t] = S[LVL2_OFF + t];

    // ---- prefetch chunk 1 ----
    float nb4[8], nb3, nb12 = 0.f;
    {
        const float* Bp = S + SIGLEN;
        const float4* B4 = reinterpret_cast<const float4*>(Bp + LVL4_OFF);
        float4 lo = B4[2 * t], hi = B4[2 * t + 1];
        nb4[0]=lo.x; nb4[1]=lo.y; nb4[2]=lo.z; nb4[3]=lo.w;
        nb4[4]=hi.x; nb4[5]=hi.y; nb4[6]=hi.z; nb4[7]=hi.w;
        nb3 = Bp[LVL3_OFF + t];
        if (t < 72) nb12 = Bp[t];
    }
    __syncthreads();

    for (int c = 1; c < NC; ++c) {
        // stage prefetched B levels 1..3 into shared
        float b4v[8];
        #pragma unroll
        for (int s = 0; s < 8; ++s) b4v[s] = nb4[s];
        float b3own = nb3;
        if (t < 72) sB[t] = nb12;
        sB[LVL3_OFF + t] = nb3;
        __syncthreads();

        // prefetch chunk c+1
        if (c + 1 < NC) {
            const float* Bp = S + (size_t)(c + 1) * SIGLEN;
            const float4* B4 = reinterpret_cast<const float4*>(Bp + LVL4_OFF);
            float4 lo = B4[2 * t], hi = B4[2 * t + 1];
            nb4[0]=lo.x; nb4[1]=lo.y; nb4[2]=lo.z; nb4[3]=lo.w;
            nb4[4]=hi.x; nb4[5]=hi.y; nb4[6]=hi.z; nb4[7]=hi.w;
            nb3 = Bp[LVL3_OFF + t];
            if (t < 72) nb12 = Bp[t];
        }

        float a1 = cL1[p];
        float a2 = cL2[t >> 3];

        // vector loads of the three B slices needed for level 4
        const float4* b3q = reinterpret_cast<const float4*>(sB + LVL3_OFF + qr * 8);
        const float4* b2r = reinterpret_cast<const float4*>(sB + LVL2_OFF + r * 8);
        const float4* b1v = reinterpret_cast<const float4*>(sB);
        float4 b3lo = b3q[0], b3hi = b3q[1];
        float4 b2lo = b2r[0], b2hi = b2r[1];
        float4 b1lo = b1v[0], b1hi = b1v[1];
        const float* f3 = &b3lo.x;  // contiguous float4 pair access below
        (void)f3;

        float b3a[8] = {b3lo.x,b3lo.y,b3lo.z,b3lo.w,b3hi.x,b3hi.y,b3hi.z,b3hi.w};
        float b2a[8] = {b2lo.x,b2lo.y,b2lo.z,b2lo.w,b2hi.x,b2hi.y,b2hi.z,b2hi.w};
        float b1a[8] = {b1lo.x,b1lo.y,b1lo.z,b1lo.w,b1hi.x,b1hi.y,b1hi.z,b1hi.w};

        #pragma unroll
        for (int s = 0; s < 8; ++s) {
            float cc = c4[s] + b4v[s];
            cc = fmaf(a1, b3a[s], cc);
            cc = fmaf(a2, b2a[s], cc);
            cc = fmaf(c3, b1a[s], cc);
            c4[s] = cc;
        }

        // level 3 (own index t = pqr): + A1[p]*B2[qr] + A2[pq]*B1[r]
        c3 = c3 + b3own + a1 * sB[LVL2_OFF + qr] + a2 * sB[r];

        // levels 1,2 (computed into regs with OLD cL*, then committed)
        float n2 = 0.f, n1 = 0.f;
        if (t < 64) n2 = cL2[t] + sB[LVL2_OFF + t] + cL1[t >> 3] * sB[t & 7];
        if (t < 8)  n1 = cL1[t] + sB[t];
        __syncthreads();
        if (t < 64) cL2[t] = n2;
        if (t < 8)  cL1[t] = n1;
        // (sB is rewritten at top of next iter, after the sync there)
        __syncthreads();
    }

    // ---- write final output: [L1 32x8][L2 32x64][L3 32x512][L4 32x4096] ----
    float* o1 = out + (size_t)b * 8;
    float* o2 = out + 256   + (size_t)b * 64;
    float* o3 = out + 2304  + (size_t)b * 512;
    float* o4 = out + 18688 + (size_t)b * 4096;
    float4* O4 = reinterpret_cast<float4*>(o4);
    O4[2 * t]     = make_float4(c4[0], c4[1], c4[2], c4[3]);
    O4[2 * t + 1] = make_float4(c4[4], c4[5], c4[6], c4[7]);
    o3[t] = c3;
    if (t < 64) o2[t] = cL2[t];
    if (t < 8)  o1[t] = cL1[t];
}

// ---------------------------------------------------------------------------
extern "C" void kernel_launch(void* const* d_in, const int* in_sizes, int n_in,
                              void* d_out, int out_size)
{
    const float* path = (const float*)d_in[0];
    float* out = (float*)d_out;

    float* buf0;
    cudaGetSymbolAddress((void**)&buf0, g_buf0);

    // 1) per-chunk signatures: 32 batches x 32 chunks
    sig_chunk_kernel<<<BATCH * NC, 512>>>(path, buf0);

    // 2) per-batch sequential Chen reduction (one block per batch)
    chen_seq_kernel<<<BATCH, 512>>>(buf0, out);
}

// round 4
// speedup vs baseline: 3.4198x; 1.0006x over previous
#include <cuda_runtime.h>
#include <cstdint>

// Problem constants
#define BATCH   32
#define PLEN    1024
#define DIM     8
#define CS      32          // increments per chunk
#define NC      32          // chunks per batch
#define SIGLEN  4680        // 8 + 64 + 512 + 4096
#define LVL2_OFF 8
#define LVL3_OFF 72
#define LVL4_OFF 584

// Scratch: chunk-signature buffer (device global — no cudaMalloc allowed)
__device__ float g_buf0[BATCH * NC * SIGLEN];   // ~19.2 MB

// ---------------------------------------------------------------------------
// Kernel 1: per-chunk signature via sequential Horner updates.
// Block = (batch, chunk). 512 threads: thread t (= p*64+q*8+r) owns
//   A4[8t..8t+7], A3[t], A2[pq] (threads with r==0 write it), scalar a1p.
// NO dynamic register-array indexing: xp/xq/xr come straight from smem.
// ---------------------------------------------------------------------------
__global__ __launch_bounds__(512) void sig_chunk_kernel(
    const float* __restrict__ path, float* __restrict__ out)
{
    int bc = blockIdx.x;
    int b  = bc >> 5;       // / NC
    int c  = bc & (NC - 1);

    __shared__ float sx[CS * DIM];   // chunk increments, 1 KB

    int t = threadIdx.x;
    {
        // 256 increments * 8 dims / 512 threads -> wait, CS*DIM = 256 floats
        if (t < CS * DIM) {
            int k   = t >> 3;
            int dim = t & 7;
            int i   = c * CS + k;
            float v = 0.0f;
            if (i < PLEN - 1) {
                const float* pp = path + ((size_t)b * PLEN + i) * DIM + dim;
                v = pp[DIM] - pp[0];
            }
            sx[t] = v;
        }
    }
    __syncthreads();

    int p = t >> 6;
    int q = (t >> 3) & 7;
    int r = t & 7;

    float a4[8] = {0.f,0.f,0.f,0.f,0.f,0.f,0.f,0.f};
    float a3 = 0.f;
    float a2 = 0.f;
    float a1p = 0.f;

    #pragma unroll 4
    for (int k = 0; k < CS; ++k) {
        const float4* sx4 = reinterpret_cast<const float4*>(sx + k * 8);
        float4 xlo = sx4[0];
        float4 xhi = sx4[1];
        float xp = sx[k * 8 + p];
        float xq = sx[k * 8 + q];
        float xr = sx[k * 8 + r];

        // Horner factors (use OLD state)
        float t4 = a3 + xr * (a2 * 0.5f + xq * fmaf(xp, (1.0f/24.0f), a1p * (1.0f/6.0f)));
        float t3 = a2 + xq * fmaf(xp, (1.0f/6.0f), a1p * 0.5f);

        a4[0] = fmaf(xlo.x, t4, a4[0]);
        a4[1] = fmaf(xlo.y, t4, a4[1]);
        a4[2] = fmaf(xlo.z, t4, a4[2]);
        a4[3] = fmaf(xlo.w, t4, a4[3]);
        a4[4] = fmaf(xhi.x, t4, a4[4]);
        a4[5] = fmaf(xhi.y, t4, a4[5]);
        a4[6] = fmaf(xhi.z, t4, a4[6]);
        a4[7] = fmaf(xhi.w, t4, a4[7]);
        a3 = fmaf(xr, t3, a3);
        a2 = fmaf(xq, fmaf(xp, 0.5f, a1p), a2);
        a1p += xp;
    }

    float* base = out + (size_t)bc * SIGLEN;
    if (t < 8) {
        // chunk level-1 = telescoping sum of increments = path[end]-path[start]
        int istart = c * CS;
        int iend   = min(istart + CS, PLEN - 1);
        const float* pb = path + (size_t)b * PLEN * DIM;
        base[t] = pb[(size_t)iend * DIM + t] - pb[(size_t)istart * DIM + t];
    }
    if (r == 0) base[LVL2_OFF + (t >> 3)] = a2;
    base[LVL3_OFF + t] = a3;
    float4* b4 = reinterpret_cast<float4*>(base + LVL4_OFF);
    b4[2 * t]     = make_float4(a4[0], a4[1], a4[2], a4[3]);
    b4[2 * t + 1] = make_float4(a4[4], a4[5], a4[6], a4[7]);
}

// ---------------------------------------------------------------------------
// Kernel 2: per-batch SEQUENTIAL Chen reduction of NC chunk signatures.
// One block per batch, 512 threads. State: L4 slice (8 regs) + L3 (1 reg)
// per thread; L1/L2 in shared. Next chunk's signature prefetched into
// registers to hide L2 latency. Writes final concatenated output.
//   C = A (x) B:  C4 = A4+B4 + A1(x)B3 + A2(x)B2 + A3(x)B1
//                 C3 = A3+B3 + A1(x)B2 + A2(x)B1
//                 C2 = A2+B2 + A1(x)B1
//                 C1 = A1+B1
// ---------------------------------------------------------------------------
__global__ __launch_bounds__(512) void chen_seq_kernel(
    const float* __restrict__ in, float* __restrict__ out)
{
    int b = blockIdx.x;
    int t = threadIdx.x;
    int p = t >> 6;
    int qr = t & 63;
    int r = t & 7;

    __shared__ float cL1[8];
    __shared__ float cL2[64];
    __shared__ float sB[584];     // B levels 1..3 of current multiplicand

    const float* S = in + (size_t)b * NC * SIGLEN;

    // ---- init state from chunk 0 ----
    float c4[8];
    {
        const float4* A4 = reinterpret_cast<const float4*>(S + LVL4_OFF);
        float4 lo = A4[2 * t], hi = A4[2 * t + 1];
        c4[0]=lo.x; c4[1]=lo.y; c4[2]=lo.z; c4[3]=lo.w;
        c4[4]=hi.x; c4[5]=hi.y; c4[6]=hi.z; c4[7]=hi.w;
    }
    float c3 = S[LVL3_OFF + t];
    if (t < 8)  cL1[t] = S[t];
    if (t < 64) cL2[t] = S[LVL2_OFF + t];

    // ---- prefetch chunk 1 ----
    float nb4[8], nb3, nb12 = 0.f;
    {
        const float* Bp = S + SIGLEN;
        const float4* B4 = reinterpret_cast<const float4*>(Bp + LVL4_OFF);
        float4 lo = B4[2 * t], hi = B4[2 * t + 1];
        nb4[0]=lo.x; nb4[1]=lo.y; nb4[2]=lo.z; nb4[3]=lo.w;
        nb4[4]=hi.x; nb4[5]=hi.y; nb4[6]=hi.z; nb4[7]=hi.w;
        nb3 = Bp[LVL3_OFF + t];
        if (t < 72) nb12 = Bp[t];
    }
    __syncthreads();

    for (int c = 1; c < NC; ++c) {
        // stage prefetched B levels 1..3 into shared
        float b4v[8];
        #pragma unroll
        for (int s = 0; s < 8; ++s) b4v[s] = nb4[s];
        float b3own = nb3;
        if (t < 72) sB[t] = nb12;
        sB[LVL3_OFF + t] = nb3;
        __syncthreads();

        // prefetch chunk c+1
        if (c + 1 < NC) {
            const float* Bp = S + (size_t)(c + 1) * SIGLEN;
            const float4* B4 = reinterpret_cast<const float4*>(Bp + LVL4_OFF);
            float4 lo = B4[2 * t], hi = B4[2 * t + 1];
            nb4[0]=lo.x; nb4[1]=lo.y; nb4[2]=lo.z; nb4[3]=lo.w;
            nb4[4]=hi.x; nb4[5]=hi.y; nb4[6]=hi.z; nb4[7]=hi.w;
            nb3 = Bp[LVL3_OFF + t];
            if (t < 72) nb12 = Bp[t];
        }

        float a1 = cL1[p];
        float a2 = cL2[t >> 3];

        // vector loads of the three B slices needed for level 4
        const float4* b3q = reinterpret_cast<const float4*>(sB + LVL3_OFF + qr * 8);
        const float4* b2r = reinterpret_cast<const float4*>(sB + LVL2_OFF + r * 8);
        const float4* b1v = reinterpret_cast<const float4*>(sB);
        float4 b3lo = b3q[0], b3hi = b3q[1];
        float4 b2lo = b2r[0], b2hi = b2r[1];
        float4 b1lo = b1v[0], b1hi = b1v[1];
        const float* f3 = &b3lo.x;  // contiguous float4 pair access below
        (void)f3;

        float b3a[8] = {b3lo.x,b3lo.y,b3lo.z,b3lo.w,b3hi.x,b3hi.y,b3hi.z,b3hi.w};
        float b2a[8] = {b2lo.x,b2lo.y,b2lo.z,b2lo.w,b2hi.x,b2hi.y,b2hi.z,b2hi.w};
        float b1a[8] = {b1lo.x,b1lo.y,b1lo.z,b1lo.w,b1hi.x,b1hi.y,b1hi.z,b1hi.w};

        #pragma unroll
        for (int s = 0; s < 8; ++s) {
            float cc = c4[s] + b4v[s];
            cc = fmaf(a1, b3a[s], cc);
            cc = fmaf(a2, b2a[s], cc);
            cc = fmaf(c3, b1a[s], cc);
            c4[s] = cc;
        }

        // level 3 (own index t = pqr): + A1[p]*B2[qr] + A2[pq]*B1[r]
        c3 = c3 + b3own + a1 * sB[LVL2_OFF + qr] + a2 * sB[r];

        // levels 1,2 (computed into regs with OLD cL*, then committed)
        float n2 = 0.f, n1 = 0.f;
        if (t < 64) n2 = cL2[t] + sB[LVL2_OFF + t] + cL1[t >> 3] * sB[t & 7];
        if (t < 8)  n1 = cL1[t] + sB[t];
        __syncthreads();
        if (t < 64) cL2[t] = n2;
        if (t < 8)  cL1[t] = n1;
        // (sB is rewritten at top of next iter, after the sync there)
        __syncthreads();
    }

    // ---- write final output: [L1 32x8][L2 32x64][L3 32x512][L4 32x4096] ----
    float* o1 = out + (size_t)b * 8;
    float* o2 = out + 256   + (size_t)b * 64;
    float* o3 = out + 2304  + (size_t)b * 512;
    float* o4 = out + 18688 + (size_t)b * 4096;
    float4* O4 = reinterpret_cast<float4*>(o4);
    O4[2 * t]     = make_float4(c4[0], c4[1], c4[2], c4[3]);
    O4[2 * t + 1] = make_float4(c4[4], c4[5], c4[6], c4[7]);
    o3[t] = c3;
    if (t < 64) o2[t] = cL2[t];
    if (t < 8)  o1[t] = cL1[t];
}

// ---------------------------------------------------------------------------
extern "C" void kernel_launch(void* const* d_in, const int* in_sizes, int n_in,
                              void* d_out, int out_size)
{
    const float* path = (const float*)d_in[0];
    float* out = (float*)d_out;

    float* buf0;
    cudaGetSymbolAddress((void**)&buf0, g_buf0);

    // 1) per-chunk signatures: 32 batches x 32 chunks
    sig_chunk_kernel<<<BATCH * NC, 512>>>(path, buf0);

    // 2) per-batch sequential Chen reduction (one block per batch)
    chen_seq_kernel<<<BATCH, 512>>>(buf0, out);
}

// round 5
// speedup vs baseline: 4.8261x; 1.4112x over previous
#include <cuda_runtime.h>
#include <cstdint>

// Problem constants
#define BATCH   32
#define PLEN    1024
#define DIM     8
#define CS      32          // increments per chunk
#define NC      32          // chunks per batch
#define SIGLEN  4680        // 8 + 64 + 512 + 4096
#define LVL2_OFF 8
#define LVL3_OFF 72
#define LVL4_OFF 584
#define GROUPS   4          // stage-A groups per batch (8 chunks each)

// Scratch (device globals — no cudaMalloc allowed)
__device__ float g_buf0[BATCH * NC * SIGLEN];       // ~19.2 MB chunk sigs
__device__ float g_buf1[BATCH * GROUPS * SIGLEN];   // ~2.4 MB partials

// ---- packed f32x2 helpers -------------------------------------------------
__device__ __forceinline__ unsigned long long fma2(
    unsigned long long a, unsigned long long b, unsigned long long c)
{
    unsigned long long d;
    asm("fma.rn.f32x2 %0, %1, %2, %3;" : "=l"(d) : "l"(a), "l"(b), "l"(c));
    return d;
}
__device__ __forceinline__ unsigned long long dup2(float x)
{
    unsigned long long d;
    asm("mov.b64 %0, {%1, %1};" : "=l"(d) : "f"(x));
    return d;
}
__device__ __forceinline__ float2 unpack2(unsigned long long v)
{
    float2 f;
    asm("mov.b64 {%0, %1}, %2;" : "=f"(f.x), "=f"(f.y) : "l"(v));
    return f;
}

// ---------------------------------------------------------------------------
// Kernel 1: per-chunk signature via sequential Horner updates.
// Block = (batch, chunk). 512 threads: thread t (= p*64+q*8+r) owns
//   A4[8t..8t+7] (as 4 packed f32x2), A3[t], A2[pq] (r==0 writes), scalar a1p.
// ---------------------------------------------------------------------------
__global__ __launch_bounds__(512) void sig_chunk_kernel(
    const float* __restrict__ path, float* __restrict__ out)
{
    int bc = blockIdx.x;
    int b  = bc >> 5;       // / NC
    int c  = bc & (NC - 1);

    __shared__ __align__(16) float sx[CS * DIM];   // chunk increments, 1 KB

    int t = threadIdx.x;
    if (t < CS * DIM) {
        int k   = t >> 3;
        int dim = t & 7;
        int i   = c * CS + k;
        float v = 0.0f;
        if (i < PLEN - 1) {
            const float* pp = path + ((size_t)b * PLEN + i) * DIM + dim;
            v = pp[DIM] - pp[0];
        }
        sx[t] = v;
    }
    __syncthreads();

    int p = t >> 6;
    int q = (t >> 3) & 7;
    int r = t & 7;

    unsigned long long a4[4] = {0ull, 0ull, 0ull, 0ull};
    float a3 = 0.f;
    float a2 = 0.f;
    float a1p = 0.f;

    #pragma unroll 4
    for (int k = 0; k < CS; ++k) {
        const ulonglong2* sx2 = reinterpret_cast<const ulonglong2*>(sx + k * 8);
        ulonglong2 xA = sx2[0];   // x0x1 , x2x3
        ulonglong2 xB = sx2[1];   // x4x5 , x6x7
        float xp = sx[k * 8 + p];
        float xq = sx[k * 8 + q];
        float xr = sx[k * 8 + r];

        // Horner factors (OLD state)
        float t4 = fmaf(xr, fmaf(xq, fmaf(xp, (1.0f/24.0f), a1p * (1.0f/6.0f)),
                                 a2 * 0.5f), a3);
        float v3 = fmaf(xp, (1.0f/6.0f), a1p * 0.5f);

        unsigned long long t42 = dup2(t4);
        a4[0] = fma2(xA.x, t42, a4[0]);
        a4[1] = fma2(xA.y, t42, a4[1]);
        a4[2] = fma2(xB.x, t42, a4[2]);
        a4[3] = fma2(xB.y, t42, a4[3]);

        a3 = fmaf(xr, fmaf(xq, v3, a2), a3);
        a2 = fmaf(xq, fmaf(xp, 0.5f, a1p), a2);
        a1p += xp;
    }

    float* base = out + (size_t)bc * SIGLEN;
    if (t < 8) {
        // chunk level-1 = telescoping sum = path[end]-path[start]
        int istart = c * CS;
        int iend   = min(istart + CS, PLEN - 1);
        const float* pb = path + (size_t)b * PLEN * DIM;
        base[t] = pb[(size_t)iend * DIM + t] - pb[(size_t)istart * DIM + t];
    }
    if (r == 0) base[LVL2_OFF + (t >> 3)] = a2;
    base[LVL3_OFF + t] = a3;
    float2 f0 = unpack2(a4[0]);
    float2 f1 = unpack2(a4[1]);
    float2 f2 = unpack2(a4[2]);
    float2 f3 = unpack2(a4[3]);
    float4* b4 = reinterpret_cast<float4*>(base + LVL4_OFF);
    b4[2 * t]     = make_float4(f0.x, f0.y, f1.x, f1.y);
    b4[2 * t + 1] = make_float4(f2.x, f2.y, f3.x, f3.y);
}

// ---------------------------------------------------------------------------
// Kernel 2: barrier-free grouped Chen reduction.
// Block reduces NB+1 consecutive signatures (accumulator = sig 0, then NB
// right-multiplies). All B levels 1..3 staged in smem up front; B level-4
// streamed per-thread with register double-buffering. L1/L2 accumulator state
// is REPLICATED in registers (a1 = A1[p], a2 = A2[pq]) so the multiply loop
// needs no __syncthreads.
//   C4 = A4 + B4 + A1(x)B3 + A2(x)B2 + A3(x)B1
//   C3 = A3 + B3 + A1(x)B2 + A2(x)B1
//   C2 = A2 + B2 + A1(x)B1 ;  C1 = A1 + B1
// ---------------------------------------------------------------------------
template <int NB, bool FINAL>
__global__ __launch_bounds__(512) void chen_group_kernel(
    const float* __restrict__ in, float* __restrict__ out)
{
    const int t  = threadIdx.x;
    const int p  = t >> 6;
    const int q  = (t >> 3) & 7;
    const int r  = t & 7;
    const int pq = t >> 3;
    const int qr = t & 63;

    __shared__ __align__(16) float sB[NB * 584];

    const float* S = in + (size_t)blockIdx.x * (NB + 1) * SIGLEN;

    // stage all B sigs' levels 1..3
    #pragma unroll
    for (int sig = 0; sig < NB; ++sig) {
        for (int off = t; off < 584; off += 512)
            sB[sig * 584 + off] = S[(size_t)(sig + 1) * SIGLEN + off];
    }

    // init accumulator from sig 0
    float c4[8];
    {
        const float4* A4 = reinterpret_cast<const float4*>(S + LVL4_OFF);
        float4 lo = A4[2 * t], hi = A4[2 * t + 1];
        c4[0]=lo.x; c4[1]=lo.y; c4[2]=lo.z; c4[3]=lo.w;
        c4[4]=hi.x; c4[5]=hi.y; c4[6]=hi.z; c4[7]=hi.w;
    }
    float c3 = S[LVL3_OFF + t];
    float a2 = S[LVL2_OFF + pq];
    float a1 = S[p];

    // prefetch first B4 slice
    float4 nlo, nhi;
    {
        const float4* B4 = reinterpret_cast<const float4*>(S + SIGLEN + LVL4_OFF);
        nlo = B4[2 * t]; nhi = B4[2 * t + 1];
    }
    __syncthreads();

    #pragma unroll
    for (int i = 0; i < NB; ++i) {
        float b4[8] = {nlo.x,nlo.y,nlo.z,nlo.w,nhi.x,nhi.y,nhi.z,nhi.w};
        if (i + 1 < NB) {
            const float4* B4 = reinterpret_cast<const float4*>(
                S + (size_t)(i + 2) * SIGLEN + LVL4_OFF);
            nlo = B4[2 * t]; nhi = B4[2 * t + 1];
        }
        const float* B = sB + i * 584;

        const float4* b3s = reinterpret_cast<const float4*>(B + LVL3_OFF + qr * 8);
        const float4* b2s = reinterpret_cast<const float4*>(B + LVL2_OFF + r * 8);
        const float4* b1s = reinterpret_cast<const float4*>(B);
        float4 w3a = b3s[0], w3b = b3s[1];
        float4 w2a = b2s[0], w2b = b2s[1];
        float4 w1a = b1s[0], w1b = b1s[1];
        float b3a[8] = {w3a.x,w3a.y,w3a.z,w3a.w,w3b.x,w3b.y,w3b.z,w3b.w};
        float b2a[8] = {w2a.x,w2a.y,w2a.z,w2a.w,w2b.x,w2b.y,w2b.z,w2b.w};
        float b1a[8] = {w1a.x,w1a.y,w1a.z,w1a.w,w1b.x,w1b.y,w1b.z,w1b.w};

        #pragma unroll
        for (int s = 0; s < 8; ++s) {
            float cc = c4[s] + b4[s];
            cc = fmaf(a1, b3a[s], cc);
            cc = fmaf(a2, b2a[s], cc);
            cc = fmaf(c3, b1a[s], cc);   // uses OLD c3
            c4[s] = cc;
        }

        float b3t  = B[LVL3_OFF + t];
        float b2qr = B[LVL2_OFF + qr];
        float b2pq = B[LVL2_OFF + pq];
        float b1r  = B[r];
        float b1q  = B[q];
        float b1p  = B[p];

        float nc3 = c3 + b3t + a1 * b2qr + a2 * b1r;   // old a1, a2
        float na2 = a2 + b2pq + a1 * b1q;              // old a1
        float na1 = a1 + b1p;
        c3 = nc3; a2 = na2; a1 = na1;
    }

    // ---- write result ----
    if (!FINAL) {
        float* O = out + (size_t)blockIdx.x * SIGLEN;
        if ((t & 63) == 0) O[p] = a1;
        if (r == 0)        O[LVL2_OFF + pq] = a2;
        O[LVL3_OFF + t] = c3;
        float4* O4 = reinterpret_cast<float4*>(O + LVL4_OFF);
        O4[2 * t]     = make_float4(c4[0], c4[1], c4[2], c4[3]);
        O4[2 * t + 1] = make_float4(c4[4], c4[5], c4[6], c4[7]);
    } else {
        // Output layout: [L1 32x8][L2 32x64][L3 32x512][L4 32x4096]
        int b = blockIdx.x;
        float* o1 = out + (size_t)b * 8;
        float* o2 = out + 256   + (size_t)b * 64;
        float* o3 = out + 2304  + (size_t)b * 512;
        float* o4 = out + 18688 + (size_t)b * 4096;
        if ((t & 63) == 0) o1[p] = a1;
        if (r == 0)        o2[pq] = a2;
        o3[t] = c3;
        float4* O4 = reinterpret_cast<float4*>(o4);
        O4[2 * t]     = make_float4(c4[0], c4[1], c4[2], c4[3]);
        O4[2 * t + 1] = make_float4(c4[4], c4[5], c4[6], c4[7]);
    }
}

// ---------------------------------------------------------------------------
extern "C" void kernel_launch(void* const* d_in, const int* in_sizes, int n_in,
                              void* d_out, int out_size)
{
    const float* path = (const float*)d_in[0];
    float* out = (float*)d_out;

    float *buf0, *buf1;
    cudaGetSymbolAddress((void**)&buf0, g_buf0);
    cudaGetSymbolAddress((void**)&buf1, g_buf1);

    // 1) per-chunk signatures: 32 batches x 32 chunks
    sig_chunk_kernel<<<BATCH * NC, 512>>>(path, buf0);

    // 2) stage A: 4 groups/batch, each reduces 8 chunks (7 multiplies)
    chen_group_kernel<7, false><<<BATCH * GROUPS, 512>>>(buf0, buf1);

    // 3) stage B: reduce 4 partials per batch (3 multiplies), final layout
    chen_group_kernel<3, true><<<BATCH, 512>>>(buf1, out);
}

// round 6
// speedup vs baseline: 7.5361x; 1.5615x over previous
#include <cuda_runtime.h>
#include <cstdint>

// Problem constants
#define BATCH   32
#define PLEN    1024
#define DIM     8
#define SIGLEN  4680        // 8 + 64 + 512 + 4096
#define LVL2_OFF 8
#define LVL3_OFF 72
#define LVL4_OFF 584
#define GROUPS   4          // groups per batch; each group = 8 chunks of 32 incs

// Dynamic smem layout (bytes)
#define S4_BYTES   (8 * 2048 * 8)            // 8 chunks x 2048 u64 (L4)  = 131072
#define SL_OFF     (S4_BYTES)                // L1..L3 per chunk: 8 x 584 floats
#define SL_BYTES   (8 * 584 * 4)             // 18688
#define SX_OFF     (SL_OFF + SL_BYTES)       // increments: 2048 floats
#define SX_BYTES   (2048 * 4)                // 8192
#define SMEM_TOTAL_BYTES (SX_OFF + SX_BYTES) // 157952

// Scratch (device global — no cudaMalloc allowed)
__device__ float g_buf1[BATCH * GROUPS * SIGLEN];   // group partial sigs

// ---- packed f32x2 helpers -------------------------------------------------
__device__ __forceinline__ unsigned long long fma2(
    unsigned long long a, unsigned long long b, unsigned long long c)
{
    unsigned long long d;
    asm("fma.rn.f32x2 %0, %1, %2, %3;" : "=l"(d) : "l"(a), "l"(b), "l"(c));
    return d;
}
__device__ __forceinline__ unsigned long long dup2(float x)
{
    unsigned long long d;
    asm("mov.b64 %0, {%1, %1};" : "=l"(d) : "f"(x));
    return d;
}
__device__ __forceinline__ float2 unpack2(unsigned long long v)
{
    float2 f;
    asm("mov.b64 {%0, %1}, %2;" : "=f"(f.x), "=f"(f.y) : "l"(v));
    return f;
}

// ---------------------------------------------------------------------------
// Fused kernel: phase 1 computes 8 chunk signatures (32 increments each),
// one (p,q) row (64 level-4 entries) per thread; phase 2 reduces the 8 chunk
// sigs with barrier-free Chen multiplies (L1/L2 accumulator replicated in
// registers). Grid = 32 batches x 4 groups; block = 512 threads.
// ---------------------------------------------------------------------------
__global__ __launch_bounds__(512) void sig_fused_kernel(
    const float* __restrict__ path, float* __restrict__ out)
{
    extern __shared__ __align__(16) char smem[];
    unsigned long long* s4 = reinterpret_cast<unsigned long long*>(smem);
    float* sL = reinterpret_cast<float*>(smem + SL_OFF);
    float* sx = reinterpret_cast<float*>(smem + SX_OFF);

    const int bx = blockIdx.x;
    const int b  = bx >> 2;
    const int g  = bx & 3;
    const int t  = threadIdx.x;
    const int sc  = t >> 6;      // chunk within group (0..7)
    const int tpq = t & 63;      // (p,q) row within chunk
    const int p   = tpq >> 3;
    const int q   = tpq & 7;

    const float* pb = path + (size_t)b * (PLEN * DIM);

    // ---- load this group's 256 increments (8 chunks x 32 x 8 dims) ----
    #pragma unroll
    for (int idx = t; idx < 2048; idx += 512) {
        int i  = g * 256 + (idx >> 3);
        int dd = idx & 7;
        float v = 0.0f;
        if (i < PLEN - 1) v = pb[(i + 1) * 8 + dd] - pb[i * 8 + dd];
        sx[idx] = v;
    }
    __syncthreads();

    const float* sxc = sx + sc * 256;

    // ---- phase 1: chunk signature, 64 L4 entries per thread ----
    unsigned long long P[32];          // a4[r][s-pair j], idx = r*4+j
    #pragma unroll
    for (int i = 0; i < 32; ++i) P[i] = 0ull;
    unsigned long long A3[4] = {0ull, 0ull, 0ull, 0ull};  // a3 pairs (2rp,2rp+1)
    float a2 = 0.f, a1p = 0.f;

    #pragma unroll 2
    for (int k = 0; k < 32; ++k) {
        ulonglong2 xa = *reinterpret_cast<const ulonglong2*>(sxc + k * 8);
        ulonglong2 xb = *reinterpret_cast<const ulonglong2*>(sxc + k * 8 + 4);
        unsigned long long Xv[4] = {xa.x, xa.y, xb.x, xb.y};
        float xp = sxc[k * 8 + p];
        float xq = sxc[k * 8 + q];

        // shared scalar chain (OLD state)
        float v      = fmaf(xp, (1.0f/24.0f), a1p * (1.0f/6.0f));
        float inner  = fmaf(xq, v, a2 * 0.5f);
        float w      = fmaf(xp, (1.0f/6.0f), a1p * 0.5f);
        float innerW = fmaf(xq, w, a2);
        a2  = fmaf(xq, fmaf(xp, 0.5f, a1p), a2);
        a1p += xp;

        unsigned long long inner2  = dup2(inner);
        unsigned long long innerW2 = dup2(innerW);

        #pragma unroll
        for (int rp = 0; rp < 4; ++rp) {
            unsigned long long t4p = fma2(Xv[rp], inner2, A3[rp]);  // OLD a3
            A3[rp] = fma2(Xv[rp], innerW2, A3[rp]);
            float2 tt = unpack2(t4p);
            unsigned long long tlo = dup2(tt.x);
            unsigned long long thi = dup2(tt.y);
            #pragma unroll
            for (int j = 0; j < 4; ++j)
                P[(2 * rp) * 4 + j] = fma2(Xv[j], tlo, P[(2 * rp) * 4 + j]);
            #pragma unroll
            for (int j = 0; j < 4; ++j)
                P[(2 * rp + 1) * 4 + j] = fma2(Xv[j], thi, P[(2 * rp + 1) * 4 + j]);
        }
    }

    // ---- store chunk signature into smem ----
    float* L = sL + sc * 584;
    if (tpq < 8) {
        int c  = g * 8 + sc;
        int i0 = c * 32;
        int i1 = min(i0 + 32, PLEN - 1);
        L[tpq] = pb[i1 * 8 + tpq] - pb[i0 * 8 + tpq];   // telescoped level-1
    }
    L[LVL2_OFF + tpq] = a2;
    #pragma unroll
    for (int rp = 0; rp < 4; ++rp) {
        float2 a3v = unpack2(A3[rp]);
        L[LVL3_OFF + tpq * 8 + 2 * rp]     = a3v.x;
        L[LVL3_OFF + tpq * 8 + 2 * rp + 1] = a3v.y;
    }
    {
        unsigned long long* s4c = s4 + sc * 2048 + tpq * 32;
        int sw = tpq & 31;
        #pragma unroll
        for (int rj = 0; rj < 32; ++rj) s4c[rj ^ sw] = P[rj];
    }
    __syncthreads();

    // ---- phase 2: barrier-free Chen reduction of 8 chunk sigs ----
    const int p2  = t >> 6;
    const int q2  = (t >> 3) & 7;
    const int r2  = t & 7;
    const int pq2 = t >> 3;
    const int qr2 = t & 63;
    const int swr = pq2 & 31;

    float c4[8];
    {
        const unsigned long long* bc = s4 + pq2 * 32;   // chunk 0
        #pragma unroll
        for (int j = 0; j < 4; ++j) {
            float2 vv = unpack2(bc[(r2 * 4 + j) ^ swr]);
            c4[2 * j]     = vv.x;
            c4[2 * j + 1] = vv.y;
        }
    }
    float c3  = sL[LVL3_OFF + t];
    float a2r = sL[LVL2_OFF + pq2];
    float a1r = sL[p2];

    #pragma unroll 1
    for (int i = 1; i < 8; ++i) {
        const float* B = sL + i * 584;

        const float4* b3s = reinterpret_cast<const float4*>(B + LVL3_OFF + qr2 * 8);
        const float4* b2s = reinterpret_cast<const float4*>(B + LVL2_OFF + r2 * 8);
        const float4* b1s = reinterpret_cast<const float4*>(B);
        float4 w3a = b3s[0], w3b = b3s[1];
        float4 w2a = b2s[0], w2b = b2s[1];
        float4 w1a = b1s[0], w1b = b1s[1];
        float b3a[8] = {w3a.x,w3a.y,w3a.z,w3a.w,w3b.x,w3b.y,w3b.z,w3b.w};
        float b2a[8] = {w2a.x,w2a.y,w2a.z,w2a.w,w2b.x,w2b.y,w2b.z,w2b.w};
        float b1a[8] = {w1a.x,w1a.y,w1a.z,w1a.w,w1b.x,w1b.y,w1b.z,w1b.w};

        float b4[8];
        {
            const unsigned long long* bc = s4 + i * 2048 + pq2 * 32;
            #pragma unroll
            for (int j = 0; j < 4; ++j) {
                float2 vv = unpack2(bc[(r2 * 4 + j) ^ swr]);
                b4[2 * j]     = vv.x;
                b4[2 * j + 1] = vv.y;
            }
        }

        #pragma unroll
        for (int s = 0; s < 8; ++s) {
            float cc = c4[s] + b4[s];
            cc = fmaf(a1r, b3a[s], cc);
            cc = fmaf(a2r, b2a[s], cc);
            cc = fmaf(c3,  b1a[s], cc);   // OLD c3
            c4[s] = cc;
        }

        float b3t  = B[LVL3_OFF + t];
        float b2qr = B[LVL2_OFF + qr2];
        float b2pq = B[LVL2_OFF + pq2];
        float b1r  = B[r2];
        float b1q  = B[q2];
        float b1p  = B[p2];

        float nc3 = c3 + b3t + a1r * b2qr + a2r * b1r;   // old a1, a2
        float na2 = a2r + b2pq + a1r * b1q;              // old a1
        float na1 = a1r + b1p;
        c3 = nc3; a2r = na2; a1r = na1;
    }

    // ---- write group partial signature ----
    float* O = out + (size_t)bx * SIGLEN;
    if ((t & 63) == 0) O[p2] = a1r;
    if (r2 == 0)       O[LVL2_OFF + pq2] = a2r;
    O[LVL3_OFF + t] = c3;
    float4* O4 = reinterpret_cast<float4*>(O + LVL4_OFF);
    O4[2 * t]     = make_float4(c4[0], c4[1], c4[2], c4[3]);
    O4[2 * t + 1] = make_float4(c4[4], c4[5], c4[6], c4[7]);
}

// ---------------------------------------------------------------------------
// Stage B: barrier-free grouped Chen reduction of the 4 group partials per
// batch (NB=3 multiplies), writing the final concatenated output layout.
// (Identical math to the proven round-5 kernel.)
// ---------------------------------------------------------------------------
template <int NB>
__global__ __launch_bounds__(512) void chen_final_kernel(
    const float* __restrict__ in, float* __restrict__ out)
{
    const int t  = threadIdx.x;
    const int p  = t >> 6;
    const int q  = (t >> 3) & 7;
    const int r  = t & 7;
    const int pq = t >> 3;
    const int qr = t & 63;

    __shared__ __align__(16) float sB[NB * 584];

    const float* S = in + (size_t)blockIdx.x * (NB + 1) * SIGLEN;

    #pragma unroll
    for (int sig = 0; sig < NB; ++sig) {
        for (int off = t; off < 584; off += 512)
            sB[sig * 584 + off] = S[(size_t)(sig + 1) * SIGLEN + off];
    }

    float c4[8];
    {
        const float4* A4 = reinterpret_cast<const float4*>(S + LVL4_OFF);
        float4 lo = A4[2 * t], hi = A4[2 * t + 1];
        c4[0]=lo.x; c4[1]=lo.y; c4[2]=lo.z; c4[3]=lo.w;
        c4[4]=hi.x; c4[5]=hi.y; c4[6]=hi.z; c4[7]=hi.w;
    }
    float c3 = S[LVL3_OFF + t];
    float a2 = S[LVL2_OFF + pq];
    float a1 = S[p];

    float4 nlo, nhi;
    {
        const float4* B4 = reinterpret_cast<const float4*>(S + SIGLEN + LVL4_OFF);
        nlo = B4[2 * t]; nhi = B4[2 * t + 1];
    }
    __syncthreads();

    #pragma unroll
    for (int i = 0; i < NB; ++i) {
        float b4[8] = {nlo.x,nlo.y,nlo.z,nlo.w,nhi.x,nhi.y,nhi.z,nhi.w};
        if (i + 1 < NB) {
            const float4* B4 = reinterpret_cast<const float4*>(
                S + (size_t)(i + 2) * SIGLEN + LVL4_OFF);
            nlo = B4[2 * t]; nhi = B4[2 * t + 1];
        }
        const float* B = sB + i * 584;

        const float4* b3s = reinterpret_cast<const float4*>(B + LVL3_OFF + qr * 8);
        const float4* b2s = reinterpret_cast<const float4*>(B + LVL2_OFF + r * 8);
        const float4* b1s = reinterpret_cast<const float4*>(B);
        float4 w3a = b3s[0], w3b = b3s[1];
        float4 w2a = b2s[0], w2b = b2s[1];
        float4 w1a = b1s[0], w1b = b1s[1];
        float b3a[8] = {w3a.x,w3a.y,w3a.z,w3a.w,w3b.x,w3b.y,w3b.z,w3b.w};
        float b2a[8] = {w2a.x,w2a.y,w2a.z,w2a.w,w2b.x,w2b.y,w2b.z,w2b.w};
        float b1a[8] = {w1a.x,w1a.y,w1a.z,w1a.w,w1b.x,w1b.y,w1b.z,w1b.w};

        #pragma unroll
        for (int s = 0; s < 8; ++s) {
            float cc = c4[s] + b4[s];
            cc = fmaf(a1, b3a[s], cc);
            cc = fmaf(a2, b2a[s], cc);
            cc = fmaf(c3, b1a[s], cc);   // OLD c3
            c4[s] = cc;
        }

        float b3t  = B[LVL3_OFF + t];
        float b2qr = B[LVL2_OFF + qr];
        float b2pq = B[LVL2_OFF + pq];
        float b1r  = B[r];
        float b1q  = B[q];
        float b1p  = B[p];

        float nc3 = c3 + b3t + a1 * b2qr + a2 * b1r;
        float na2 = a2 + b2pq + a1 * b1q;
        float na1 = a1 + b1p;
        c3 = nc3; a2 = na2; a1 = na1;
    }

    // final output layout: [L1 32x8][L2 32x64][L3 32x512][L4 32x4096]
    int b = blockIdx.x;
    float* o1 = out + (size_t)b * 8;
    float* o2 = out + 256   + (size_t)b * 64;
    float* o3 = out + 2304  + (size_t)b * 512;
    float* o4 = out + 18688 + (size_t)b * 4096;
    if ((t & 63) == 0) o1[p] = a1;
    if (r == 0)        o2[pq] = a2;
    o3[t] = c3;
    float4* O4 = reinterpret_cast<float4*>(o4);
    O4[2 * t]     = make_float4(c4[0], c4[1], c4[2], c4[3]);
    O4[2 * t + 1] = make_float4(c4[4], c4[5], c4[6], c4[7]);
}

// ---------------------------------------------------------------------------
extern "C" void kernel_launch(void* const* d_in, const int* in_sizes, int n_in,
                              void* d_out, int out_size)
{
    const float* path = (const float*)d_in[0];
    float* out = (float*)d_out;

    float* buf1;
    cudaGetSymbolAddress((void**)&buf1, g_buf1);

    cudaFuncSetAttribute(sig_fused_kernel,
                         cudaFuncAttributeMaxDynamicSharedMemorySize,
                         SMEM_TOTAL_BYTES);

    // 1) fused: chunk signatures + in-block group reduction (8 chunks/group)
    sig_fused_kernel<<<BATCH * GROUPS, 512, SMEM_TOTAL_BYTES>>>(path, buf1);

    // 2) final: reduce 4 group partials per batch, write final layout
    chen_final_kernel<3><<<BATCH, 512>>>(buf1, out);
}

// round 7
// speedup vs baseline: 8.1220x; 1.0777x over previous
#include <cuda_runtime.h>
#include <cstdint>

// Problem constants
#define BATCH   32
#define PLEN    1024
#define DIM     8
#define SIGLEN  4680        // 8 + 64 + 512 + 4096
#define LVL2_OFF 8
#define LVL3_OFF 72
#define LVL4_OFF 584
#define GROUPS   4          // groups per batch; each group = 8 chunks of 32 incs

// Dynamic smem layout (bytes)
#define S4_BYTES   (8 * 2048 * 8)            // 8 chunks x 2048 u64 (L4)  = 131072
#define SL_OFF     (S4_BYTES)                // L1..L3 per chunk: 8 x 584 floats
#define SL_BYTES   (8 * 584 * 4)             // 18688
#define SX_OFF     (SL_OFF + SL_BYTES)       // increments: 2048 floats
#define SX_BYTES   (2048 * 4)                // 8192
#define SMEM_TOTAL_BYTES (SX_OFF + SX_BYTES) // 157952

// Scratch (device globals — no cudaMalloc allowed)
__device__ float g_buf1[BATCH * GROUPS * SIGLEN];   // group partial sigs (g=1..3 used)
__device__ int   g_flags[BATCH];                    // zero-init; reset by leader

// ---- packed f32x2 helpers -------------------------------------------------
__device__ __forceinline__ unsigned long long fma2(
    unsigned long long a, unsigned long long b, unsigned long long c)
{
    unsigned long long d;
    asm("fma.rn.f32x2 %0, %1, %2, %3;" : "=l"(d) : "l"(a), "l"(b), "l"(c));
    return d;
}
__device__ __forceinline__ unsigned long long dup2(float x)
{
    unsigned long long d;
    asm("mov.b64 %0, {%1, %1};" : "=l"(d) : "f"(x));
    return d;
}
__device__ __forceinline__ float2 unpack2(unsigned long long v)
{
    float2 f;
    asm("mov.b64 {%0, %1}, %2;" : "=f"(f.x), "=f"(f.y) : "l"(v));
    return f;
}

// ---------------------------------------------------------------------------
// Single persistent kernel.
// Phase 1: 8 chunk signatures per block (32 increments each), one (p,q) row
//          (64 level-4 entries) per thread.
// Phase 2: barrier-free in-block Chen reduction of the 8 chunk sigs.
// Phase 3: blocks g=1..3 publish partials (fence + atomic arrive); the g=0
//          leader block spins, then right-multiplies the 3 partials from L2
//          and writes the final concatenated output. Grid = 128 blocks, all
//          co-resident (1 block/SM) -> handoff cannot deadlock.
// ---------------------------------------------------------------------------
__global__ __launch_bounds__(512) void sig_onekernel(
    const float* __restrict__ path, float* __restrict__ partials,
    int* __restrict__ flags, float* __restrict__ out)
{
    extern __shared__ __align__(16) char smem[];
    unsigned long long* s4 = reinterpret_cast<unsigned long long*>(smem);
    float* sL = reinterpret_cast<float*>(smem + SL_OFF);
    float* sx = reinterpret_cast<float*>(smem + SX_OFF);

    const int bx = blockIdx.x;
    const int b  = bx >> 2;
    const int g  = bx & 3;
    const int t  = threadIdx.x;
    const int sc  = t >> 6;      // chunk within group (0..7)
    const int tpq = t & 63;      // (p,q) row within chunk
    const int p   = tpq >> 3;
    const int q   = tpq & 7;

    const float* pb = path + (size_t)b * (PLEN * DIM);

    // ---- load this group's 256 increments (8 chunks x 32 x 8 dims) ----
    #pragma unroll
    for (int idx = t; idx < 2048; idx += 512) {
        int i  = g * 256 + (idx >> 3);
        int dd = idx & 7;
        float v = 0.0f;
        if (i < PLEN - 1) v = pb[(i + 1) * 8 + dd] - pb[i * 8 + dd];
        sx[idx] = v;
    }
    __syncthreads();

    const float* sxc = sx + sc * 256;

    // ---- phase 1: chunk signature, 64 L4 entries per thread ----
    unsigned long long P[32];          // a4[r][s-pair j], idx = r*4+j
    #pragma unroll
    for (int i = 0; i < 32; ++i) P[i] = 0ull;
    unsigned long long A3[4] = {0ull, 0ull, 0ull, 0ull};  // a3 pairs (2rp,2rp+1)
    float a2 = 0.f, a1p = 0.f;

    #pragma unroll 2
    for (int k = 0; k < 32; ++k) {
        ulonglong2 xa = *reinterpret_cast<const ulonglong2*>(sxc + k * 8);
        ulonglong2 xb = *reinterpret_cast<const ulonglong2*>(sxc + k * 8 + 4);
        unsigned long long Xv[4] = {xa.x, xa.y, xb.x, xb.y};
        float xp = sxc[k * 8 + p];
        float xq = sxc[k * 8 + q];

        // shared scalar chain (OLD state)
        float v      = fmaf(xp, (1.0f/24.0f), a1p * (1.0f/6.0f));
        float inner  = fmaf(xq, v, a2 * 0.5f);
        float w      = fmaf(xp, (1.0f/6.0f), a1p * 0.5f);
        float innerW = fmaf(xq, w, a2);
        a2  = fmaf(xq, fmaf(xp, 0.5f, a1p), a2);
        a1p += xp;

        unsigned long long inner2  = dup2(inner);
        unsigned long long innerW2 = dup2(innerW);

        #pragma unroll
        for (int rp = 0; rp < 4; ++rp) {
            unsigned long long t4p = fma2(Xv[rp], inner2, A3[rp]);  // OLD a3
            A3[rp] = fma2(Xv[rp], innerW2, A3[rp]);
            float2 tt = unpack2(t4p);
            unsigned long long tlo = dup2(tt.x);
            unsigned long long thi = dup2(tt.y);
            #pragma unroll
            for (int j = 0; j < 4; ++j)
                P[(2 * rp) * 4 + j] = fma2(Xv[j], tlo, P[(2 * rp) * 4 + j]);
            #pragma unroll
            for (int j = 0; j < 4; ++j)
                P[(2 * rp + 1) * 4 + j] = fma2(Xv[j], thi, P[(2 * rp + 1) * 4 + j]);
        }
    }

    // ---- store chunk signature into smem ----
    float* L = sL + sc * 584;
    if (tpq < 8) {
        int c  = g * 8 + sc;
        int i0 = c * 32;
        int i1 = min(i0 + 32, PLEN - 1);
        L[tpq] = pb[i1 * 8 + tpq] - pb[i0 * 8 + tpq];   // telescoped level-1
    }
    L[LVL2_OFF + tpq] = a2;
    #pragma unroll
    for (int rp = 0; rp < 4; ++rp) {
        float2 a3v = unpack2(A3[rp]);
        L[LVL3_OFF + tpq * 8 + 2 * rp]     = a3v.x;
        L[LVL3_OFF + tpq * 8 + 2 * rp + 1] = a3v.y;
    }
    {
        unsigned long long* s4c = s4 + sc * 2048 + tpq * 32;
        int sw = tpq & 31;
        #pragma unroll
        for (int rj = 0; rj < 32; ++rj) s4c[rj ^ sw] = P[rj];
    }
    __syncthreads();

    // ---- phase 2: barrier-free Chen reduction of 8 chunk sigs ----
    const int p2  = t >> 6;
    const int q2  = (t >> 3) & 7;
    const int r2  = t & 7;
    const int pq2 = t >> 3;
    const int qr2 = t & 63;
    const int swr = pq2 & 31;

    float c4[8];
    {
        const unsigned long long* bc = s4 + pq2 * 32;   // chunk 0
        #pragma unroll
        for (int j = 0; j < 4; ++j) {
            float2 vv = unpack2(bc[(r2 * 4 + j) ^ swr]);
            c4[2 * j]     = vv.x;
            c4[2 * j + 1] = vv.y;
        }
    }
    float c3  = sL[LVL3_OFF + t];
    float a2r = sL[LVL2_OFF + pq2];
    float a1r = sL[p2];

    #pragma unroll 1
    for (int i = 1; i < 8; ++i) {
        const float* B = sL + i * 584;

        const float4* b3s = reinterpret_cast<const float4*>(B + LVL3_OFF + qr2 * 8);
        const float4* b2s = reinterpret_cast<const float4*>(B + LVL2_OFF + r2 * 8);
        const float4* b1s = reinterpret_cast<const float4*>(B);
        float4 w3a = b3s[0], w3b = b3s[1];
        float4 w2a = b2s[0], w2b = b2s[1];
        float4 w1a = b1s[0], w1b = b1s[1];
        float b3a[8] = {w3a.x,w3a.y,w3a.z,w3a.w,w3b.x,w3b.y,w3b.z,w3b.w};
        float b2a[8] = {w2a.x,w2a.y,w2a.z,w2a.w,w2b.x,w2b.y,w2b.z,w2b.w};
        float b1a[8] = {w1a.x,w1a.y,w1a.z,w1a.w,w1b.x,w1b.y,w1b.z,w1b.w};

        float b4[8];
        {
            const unsigned long long* bc = s4 + i * 2048 + pq2 * 32;
            #pragma unroll
            for (int j = 0; j < 4; ++j) {
                float2 vv = unpack2(bc[(r2 * 4 + j) ^ swr]);
                b4[2 * j]     = vv.x;
                b4[2 * j + 1] = vv.y;
            }
        }

        #pragma unroll
        for (int s = 0; s < 8; ++s) {
            float cc = c4[s] + b4[s];
            cc = fmaf(a1r, b3a[s], cc);
            cc = fmaf(a2r, b2a[s], cc);
            cc = fmaf(c3,  b1a[s], cc);   // OLD c3
            c4[s] = cc;
        }

        float b3t  = B[LVL3_OFF + t];
        float b2qr = B[LVL2_OFF + qr2];
        float b2pq = B[LVL2_OFF + pq2];
        float b1r  = B[r2];
        float b1q  = B[q2];
        float b1p  = B[p2];

        float nc3 = c3 + b3t + a1r * b2qr + a2r * b1r;   // old a1, a2
        float na2 = a2r + b2pq + a1r * b1q;              // old a1
        float na1 = a1r + b1p;
        c3 = nc3; a2r = na2; a1r = na1;
    }

    // ---- phase 3: handoff ----
    if (g != 0) {
        // publish group partial, arrive on flag, exit
        float* O = partials + (size_t)bx * SIGLEN;
        if ((t & 63) == 0) O[p2] = a1r;
        if (r2 == 0)       O[LVL2_OFF + pq2] = a2r;
        O[LVL3_OFF + t] = c3;
        float4* O4 = reinterpret_cast<float4*>(O + LVL4_OFF);
        O4[2 * t]     = make_float4(c4[0], c4[1], c4[2], c4[3]);
        O4[2 * t + 1] = make_float4(c4[4], c4[5], c4[6], c4[7]);
        __threadfence();
        __syncthreads();
        if (t == 0) atomicAdd(&flags[b], 1);
        return;
    }

    // leader: wait for the 3 sibling groups
    if (t == 0) {
        while (atomicAdd(&flags[b], 0) < 3) __nanosleep(64);
        flags[b] = 0;            // reset for next replay
        __threadfence();
    }
    __syncthreads();

    // stage the 3 partials' levels 1..3 into smem (reuse sL)
    const float* PS = partials + (size_t)(b * GROUPS) * SIGLEN;
    #pragma unroll
    for (int j = 1; j < GROUPS; ++j) {
        const float* Bp = PS + (size_t)j * SIGLEN;
        for (int off = t; off < 584; off += 512)
            sL[(j - 1) * 584 + off] = __ldcg(Bp + off);
    }
    // prefetch partial 1's L4 slice
    float4 nlo, nhi;
    {
        const float4* B4 = reinterpret_cast<const float4*>(PS + SIGLEN + LVL4_OFF);
        nlo = __ldcg(B4 + 2 * t); nhi = __ldcg(B4 + 2 * t + 1);
    }
    __syncthreads();

    #pragma unroll
    for (int i = 0; i < 3; ++i) {
        float b4[8] = {nlo.x,nlo.y,nlo.z,nlo.w,nhi.x,nhi.y,nhi.z,nhi.w};
        if (i + 1 < 3) {
            const float4* B4 = reinterpret_cast<const float4*>(
                PS + (size_t)(i + 2) * SIGLEN + LVL4_OFF);
            nlo = __ldcg(B4 + 2 * t); nhi = __ldcg(B4 + 2 * t + 1);
        }
        const float* B = sL + i * 584;

        const float4* b3s = reinterpret_cast<const float4*>(B + LVL3_OFF + qr2 * 8);
        const float4* b2s = reinterpret_cast<const float4*>(B + LVL2_OFF + r2 * 8);
        const float4* b1s = reinterpret_cast<const float4*>(B);
        float4 w3a = b3s[0], w3b = b3s[1];
        float4 w2a = b2s[0], w2b = b2s[1];
        float4 w1a = b1s[0], w1b = b1s[1];
        float b3a[8] = {w3a.x,w3a.y,w3a.z,w3a.w,w3b.x,w3b.y,w3b.z,w3b.w};
        float b2a[8] = {w2a.x,w2a.y,w2a.z,w2a.w,w2b.x,w2b.y,w2b.z,w2b.w};
        float b1a[8] = {w1a.x,w1a.y,w1a.z,w1a.w,w1b.x,w1b.y,w1b.z,w1b.w};

        #pragma unroll
        for (int s = 0; s < 8; ++s) {
            float cc = c4[s] + b4[s];
            cc = fmaf(a1r, b3a[s], cc);
            cc = fmaf(a2r, b2a[s], cc);
            cc = fmaf(c3,  b1a[s], cc);   // OLD c3
            c4[s] = cc;
        }

        float b3t  = B[LVL3_OFF + t];
        float b2qr = B[LVL2_OFF + qr2];
        float b2pq = B[LVL2_OFF + pq2];
        float b1r  = B[r2];
        float b1q  = B[q2];
        float b1p  = B[p2];

        float nc3 = c3 + b3t + a1r * b2qr + a2r * b1r;
        float na2 = a2r + b2pq + a1r * b1q;
        float na1 = a1r + b1p;
        c3 = nc3; a2r = na2; a1r = na1;
    }

    // final output layout: [L1 32x8][L2 32x64][L3 32x512][L4 32x4096]
    float* o1 = out + (size_t)b * 8;
    float* o2 = out + 256   + (size_t)b * 64;
    float* o3 = out + 2304  + (size_t)b * 512;
    float* o4 = out + 18688 + (size_t)b * 4096;
    if ((t & 63) == 0) o1[p2] = a1r;
    if (r2 == 0)       o2[pq2] = a2r;
    o3[t] = c3;
    float4* O4 = reinterpret_cast<float4*>(o4);
    O4[2 * t]     = make_float4(c4[0], c4[1], c4[2], c4[3]);
    O4[2 * t + 1] = make_float4(c4[4], c4[5], c4[6], c4[7]);
}

// ---------------------------------------------------------------------------
extern "C" void kernel_launch(void* const* d_in, const int* in_sizes, int n_in,
                              void* d_out, int out_size)
{
    const float* path = (const float*)d_in[0];
    float* out = (float*)d_out;

    float* buf1;
    int* flags;
    cudaGetSymbolAddress((void**)&buf1, g_buf1);
    cudaGetSymbolAddress((void**)&flags, g_flags);

    cudaFuncSetAttribute(sig_onekernel,
                         cudaFuncAttributeMaxDynamicSharedMemorySize,
                         SMEM_TOTAL_BYTES);

    // single launch: chunk sigs + in-block reduce + in-grid final handoff
    sig_onekernel<<<BATCH * GROUPS, 512, SMEM_TOTAL_BYTES>>>(path, buf1, flags, out);
}